// round 16
// baseline (speedup 1.0000x reference)
#include <cuda_runtime.h>
#include <cuda_bf16.h>
#include <cuda_fp16.h>
#include <math.h>
#include <stdint.h>

#define LSEQ 4096
#define HIDDEN 4096
#define NH 32
#define NKV 8
#define DH 128
#define CHUNK 128
#define NCHUNK 32
#define QDIM 4096
#define KVDIM 1024
#define PADA 130

// ---------------- scratch (device globals: no allocations allowed) ----------------
__device__ float g_q[(size_t)LSEQ * QDIM];
__device__ float g_k[(size_t)LSEQ * KVDIM];
__device__ float g_v[(size_t)LSEQ * KVDIM];
__device__ __half g_gateh[(size_t)LSEQ * QDIM];
__device__ float g_dt[(size_t)LSEQ * NH];
__device__ float g_G[(size_t)NH * LSEQ];
__device__ __half g_S[(size_t)NH * NCHUNK * CHUNK * CHUNK];
__device__ float g_cs[(size_t)NH * NCHUNK * DH * DH];
__device__ float g_prev[(size_t)NH * NCHUNK * DH * DH];
__device__ float g_ctab[LSEQ * 64];
__device__ float g_stab[LSEQ * 64];

// bf16 hi/lo split operands (Q/K/V path)
__device__ __nv_bfloat16 g_hsh[(size_t)LSEQ * HIDDEN];
__device__ __nv_bfloat16 g_hsl[(size_t)LSEQ * HIDDEN];
__device__ __nv_bfloat16 g_Wqh[(size_t)QDIM * HIDDEN];
__device__ __nv_bfloat16 g_Wql[(size_t)QDIM * HIDDEN];
__device__ __nv_bfloat16 g_Wkh[(size_t)KVDIM * HIDDEN];
__device__ __nv_bfloat16 g_Wkl[(size_t)KVDIM * HIDDEN];
__device__ __nv_bfloat16 g_Wvh[(size_t)KVDIM * HIDDEN];
__device__ __nv_bfloat16 g_Wvl[(size_t)KVDIM * HIDDEN];

// fp16 operands (gate / output path)
__device__ __half g_hsfh[(size_t)LSEQ * HIDDEN];
__device__ __half g_hsfl[(size_t)LSEQ * HIDDEN];
__device__ __half g_Wgc[(size_t)QDIM * HIDDEN];
__device__ __half g_Woc[(size_t)HIDDEN * QDIM];
__device__ __half g_yfh[(size_t)LSEQ * QDIM];
__device__ __half g_yfl[(size_t)LSEQ * QDIM];

__device__ __forceinline__ uint32_t smu32(const void* p) {
    return (uint32_t)__cvta_generic_to_shared(p);
}

// ---------------- merged hs converter: one read -> bf16 split + fp16 split --------
__global__ void cvt_hs_all(const float* __restrict__ x)
{
    size_t i = ((size_t)blockIdx.x * 256 + threadIdx.x) * 4;
    float4 v = *(const float4*)(x + i);

    __nv_bfloat16 bh0 = __float2bfloat16(v.x);
    __nv_bfloat16 bh1 = __float2bfloat16(v.y);
    __nv_bfloat16 bh2 = __float2bfloat16(v.z);
    __nv_bfloat16 bh3 = __float2bfloat16(v.w);
    __nv_bfloat16 bl0 = __float2bfloat16(v.x - __bfloat162float(bh0));
    __nv_bfloat16 bl1 = __float2bfloat16(v.y - __bfloat162float(bh1));
    __nv_bfloat16 bl2 = __float2bfloat16(v.z - __bfloat162float(bh2));
    __nv_bfloat16 bl3 = __float2bfloat16(v.w - __bfloat162float(bh3));
    __nv_bfloat162 bp0(bh0, bh1), bp1(bh2, bh3), bq0(bl0, bl1), bq1(bl2, bl3);
    uint2 bu, bv;
    bu.x = *(uint32_t*)&bp0; bu.y = *(uint32_t*)&bp1;
    bv.x = *(uint32_t*)&bq0; bv.y = *(uint32_t*)&bq1;
    *(uint2*)(g_hsh + i) = bu;
    *(uint2*)(g_hsl + i) = bv;

    __half fh0 = __float2half_rn(v.x);
    __half fh1 = __float2half_rn(v.y);
    __half fh2 = __float2half_rn(v.z);
    __half fh3 = __float2half_rn(v.w);
    __half fl0 = __float2half_rn(v.x - __half2float(fh0));
    __half fl1 = __float2half_rn(v.y - __half2float(fh1));
    __half fl2 = __float2half_rn(v.z - __half2float(fh2));
    __half fl3 = __float2half_rn(v.w - __half2float(fh3));
    __half2 fp0(fh0, fh1), fp1(fh2, fh3), fq0(fl0, fl1), fq1(fl2, fl3);
    uint2 fu, fv;
    fu.x = *(uint32_t*)&fp0; fu.y = *(uint32_t*)&fp1;
    fv.x = *(uint32_t*)&fq0; fv.y = *(uint32_t*)&fq1;
    *(uint2*)(g_hsfh + i) = fu;
    *(uint2*)(g_hsfl + i) = fv;
}

// ---------------- fp32 -> (hi,lo) bf16 split --------------------------------------
__global__ void cvt_split(const float* __restrict__ x,
                          __nv_bfloat16* __restrict__ hi,
                          __nv_bfloat16* __restrict__ lo, size_t n)
{
    size_t i = ((size_t)blockIdx.x * 256 + threadIdx.x) * 4;
    if (i >= n) return;
    float4 v = *(const float4*)(x + i);
    __nv_bfloat16 h0 = __float2bfloat16(v.x);
    __nv_bfloat16 h1 = __float2bfloat16(v.y);
    __nv_bfloat16 h2 = __float2bfloat16(v.z);
    __nv_bfloat16 h3 = __float2bfloat16(v.w);
    __nv_bfloat16 l0 = __float2bfloat16(v.x - __bfloat162float(h0));
    __nv_bfloat16 l1 = __float2bfloat16(v.y - __bfloat162float(h1));
    __nv_bfloat16 l2 = __float2bfloat16(v.z - __bfloat162float(h2));
    __nv_bfloat16 l3 = __float2bfloat16(v.w - __bfloat162float(h3));
    __nv_bfloat162 hp0(h0, h1), hp1(h2, h3), lp0(l0, l1), lp1(l2, l3);
    uint2 hu, lu;
    hu.x = *(uint32_t*)&hp0; hu.y = *(uint32_t*)&hp1;
    lu.x = *(uint32_t*)&lp0; lu.y = *(uint32_t*)&lp1;
    *(uint2*)(hi + i) = hu;
    *(uint2*)(lo + i) = lu;
}

// ---------------- fp32 -> fp16 single ---------------------------------------------
__global__ void cvt_h(const float* __restrict__ x, __half* __restrict__ o, size_t n)
{
    size_t i = ((size_t)blockIdx.x * 256 + threadIdx.x) * 4;
    if (i >= n) return;
    float4 v = *(const float4*)(x + i);
    __half2 a = __floats2half2_rn(v.x, v.y);
    __half2 b = __floats2half2_rn(v.z, v.w);
    uint2 u;
    u.x = *(uint32_t*)&a; u.y = *(uint32_t*)&b;
    *(uint2*)(o + i) = u;
}

// ---------------- GEMM config (round-10 measured best: 8 warps, 64x32 tile) -------
#define BMt 128
#define BNt 128
#define BKt 64
#define ASTG_B (BMt * 128)
#define BSTG_B (BNt * 128)
#define STG_B  (ASTG_B + BSTG_B)          // 32768
#define GEMM_SMEM (2 * STG_B)             // 65536
#define GEMM_SMEM_ROPE (128 * 132 * 4)    // 67584 (>= GEMM_SMEM)

// ---------------- bf16 3-pass GEMM (templated: optional fused RoPE epilogue) ------
template <int ROPE>
__global__ __launch_bounds__(256, 2) void gemm_hmma3_t(
    const __nv_bfloat16* __restrict__ Ah, const __nv_bfloat16* __restrict__ Al,
    const __nv_bfloat16* __restrict__ Bh, const __nv_bfloat16* __restrict__ Bl,
    float* __restrict__ C, int Ntot, int K)
{
    extern __shared__ char smraw[];
    const int tid  = threadIdx.x;
    const int lane = tid & 31;
    const int wid  = tid >> 5;
    const int wm   = wid & 1;
    const int wn   = wid >> 1;
    const int bm   = blockIdx.y * BMt;
    const int bn   = blockIdx.x * BNt;

    const uint32_t smbase = smu32(smraw);
    const int ldrow = tid >> 3;
    const int ldcc  = tid & 7;

    const int TSEG = K >> 6;
    const int T = 3 * TSEG;

    float acc[4][4][4];
#pragma unroll
    for (int a = 0; a < 4; a++)
#pragma unroll
        for (int b = 0; b < 4; b++)
#pragma unroll
            for (int c = 0; c < 4; c++) acc[a][b][c] = 0.f;

    auto load_stage = [&](int t) {
        const int s = t & 1;
        const int seg = t / TSEG;
        const int k0 = (t - seg * TSEG) * BKt;
        const __nv_bfloat16* Ag = (seg == 1) ? Al : Ah;
        const __nv_bfloat16* Bg = (seg == 2) ? Bl : Bh;
        const uint32_t abase = smbase + s * STG_B;
        const uint32_t bbase = abase + ASTG_B;
#pragma unroll
        for (int i = 0; i < 4; i++) {
            int row = ldrow + i * 32;
            uint32_t sa = abase + row * 128 + ((ldcc ^ (row & 7)) << 4);
            const void* g = Ag + (size_t)(bm + row) * K + k0 + ldcc * 8;
            asm volatile("cp.async.cg.shared.global [%0], [%1], 16;"
                         :: "r"(sa), "l"(g));
        }
#pragma unroll
        for (int i = 0; i < 4; i++) {
            int row = ldrow + i * 32;
            uint32_t sa = bbase + row * 128 + ((ldcc ^ (row & 7)) << 4);
            const void* g = Bg + (size_t)(bn + row) * K + k0 + ldcc * 8;
            asm volatile("cp.async.cg.shared.global [%0], [%1], 16;"
                         :: "r"(sa), "l"(g));
        }
    };

    load_stage(0);
    asm volatile("cp.async.commit_group;");

    const int lr  = lane & 7;
    const int sub = lane >> 3;

    for (int t = 0; t < T; ++t) {
        if (t + 1 < T) load_stage(t + 1);
        asm volatile("cp.async.commit_group;");
        asm volatile("cp.async.wait_group 1;");
        __syncthreads();

        const int s = t & 1;
        const uint32_t abase = smbase + s * STG_B;
        const uint32_t bbase = abase + ASTG_B;

#pragma unroll
        for (int k16 = 0; k16 < 4; k16++) {
            uint32_t af[4][4];
            uint32_t bf[4][2];
#pragma unroll
            for (int mt = 0; mt < 4; mt++) {
                int row = wm * 64 + mt * 16 + lr + (sub & 1) * 8;
                int ch  = k16 * 2 + (sub >> 1);
                uint32_t ad = abase + row * 128 + ((ch ^ (row & 7)) << 4);
                asm volatile(
                    "ldmatrix.sync.aligned.m8n8.x4.shared.b16 {%0,%1,%2,%3}, [%4];"
                    : "=r"(af[mt][0]), "=r"(af[mt][1]),
                      "=r"(af[mt][2]), "=r"(af[mt][3]) : "r"(ad));
            }
#pragma unroll
            for (int np = 0; np < 2; np++) {
                int row = wn * 32 + np * 16 + lr + (sub >> 1) * 8;
                int ch  = k16 * 2 + (sub & 1);
                uint32_t bd = bbase + row * 128 + ((ch ^ (row & 7)) << 4);
                asm volatile(
                    "ldmatrix.sync.aligned.m8n8.x4.shared.b16 {%0,%1,%2,%3}, [%4];"
                    : "=r"(bf[np * 2][0]), "=r"(bf[np * 2][1]),
                      "=r"(bf[np * 2 + 1][0]), "=r"(bf[np * 2 + 1][1]) : "r"(bd));
            }
#pragma unroll
            for (int mt = 0; mt < 4; mt++)
#pragma unroll
                for (int nt = 0; nt < 4; nt++)
                    asm volatile(
                        "mma.sync.aligned.m16n8k16.row.col.f32.bf16.bf16.f32 "
                        "{%0,%1,%2,%3}, {%4,%5,%6,%7}, {%8,%9}, {%0,%1,%2,%3};"
                        : "+f"(acc[mt][nt][0]), "+f"(acc[mt][nt][1]),
                          "+f"(acc[mt][nt][2]), "+f"(acc[mt][nt][3])
                        : "r"(af[mt][0]), "r"(af[mt][1]),
                          "r"(af[mt][2]), "r"(af[mt][3]),
                          "r"(bf[nt][0]), "r"(bf[nt][1]));
        }
        __syncthreads();
    }

    if (ROPE == 0) {
        const int crow0 = bm + wm * 64 + (lane >> 2);
        const int ccol0 = bn + wn * 32 + (lane & 3) * 2;
#pragma unroll
        for (int mt = 0; mt < 4; mt++) {
#pragma unroll
            for (int nt = 0; nt < 4; nt++) {
                float* p0 = C + (size_t)(crow0 + mt * 16) * Ntot + ccol0 + nt * 8;
                float* p1 = p0 + (size_t)8 * Ntot;
                *(float2*)p0 = make_float2(acc[mt][nt][0], acc[mt][nt][1]);
                *(float2*)p1 = make_float2(acc[mt][nt][2], acc[mt][nt][3]);
            }
        }
    } else {
        // fused RoPE epilogue: stage tile in smem, rotate (e, e+64) pairs, write C.
        float* Ssm = (float*)smraw;             // 128 x 132 fp32
        const int crl0 = wm * 64 + (lane >> 2);
        const int ccl0 = wn * 32 + (lane & 3) * 2;
        __syncthreads();
#pragma unroll
        for (int mt = 0; mt < 4; mt++) {
#pragma unroll
            for (int nt = 0; nt < 4; nt++) {
                int r0 = crl0 + mt * 16;
                int c0 = ccl0 + nt * 8;
                Ssm[r0 * 132 + c0 + 0] = acc[mt][nt][0];
                Ssm[r0 * 132 + c0 + 1] = acc[mt][nt][1];
                Ssm[(r0 + 8) * 132 + c0 + 0] = acc[mt][nt][2];
                Ssm[(r0 + 8) * 132 + c0 + 1] = acc[mt][nt][3];
            }
        }
        __syncthreads();
        for (int idx = tid; idx < 128 * 64; idx += 256) {
            int row = idx >> 6, e = idx & 63;
            int l = bm + row;
            float c = g_ctab[(l << 6) + e];
            float s = g_stab[(l << 6) + e];
            float x0 = Ssm[row * 132 + e];
            float x1 = Ssm[row * 132 + e + 64];
            C[(size_t)l * Ntot + bn + e]      = x0 * c - x1 * s;
            C[(size_t)l * Ntot + bn + e + 64] = x1 * c + x0 * s;
        }
    }
}

// ---------------- fp16 2-pass GEMM -> fp32 C (output path) ------------------------
__global__ __launch_bounds__(256, 2) void gemm_hmma2h(
    const __half* __restrict__ Ah, const __half* __restrict__ Al,
    const __half* __restrict__ B,
    float* __restrict__ C, int Ntot, int K)
{
    extern __shared__ char smraw[];
    const int tid  = threadIdx.x;
    const int lane = tid & 31;
    const int wid  = tid >> 5;
    const int wm   = wid & 1;
    const int wn   = wid >> 1;
    const int bm   = blockIdx.y * BMt;
    const int bn   = blockIdx.x * BNt;

    const uint32_t smbase = smu32(smraw);
    const int ldrow = tid >> 3;
    const int ldcc  = tid & 7;

    const int TSEG = K >> 6;
    const int T = 2 * TSEG;

    float acc[4][4][4];
#pragma unroll
    for (int a = 0; a < 4; a++)
#pragma unroll
        for (int b = 0; b < 4; b++)
#pragma unroll
            for (int c = 0; c < 4; c++) acc[a][b][c] = 0.f;

    auto load_stage = [&](int t) {
        const int s = t & 1;
        const int seg = t / TSEG;
        const int k0 = (t - seg * TSEG) * BKt;
        const __half* Ag = seg ? Al : Ah;
        const uint32_t abase = smbase + s * STG_B;
        const uint32_t bbase = abase + ASTG_B;
#pragma unroll
        for (int i = 0; i < 4; i++) {
            int row = ldrow + i * 32;
            uint32_t sa = abase + row * 128 + ((ldcc ^ (row & 7)) << 4);
            const void* g = Ag + (size_t)(bm + row) * K + k0 + ldcc * 8;
            asm volatile("cp.async.cg.shared.global [%0], [%1], 16;"
                         :: "r"(sa), "l"(g));
        }
#pragma unroll
        for (int i = 0; i < 4; i++) {
            int row = ldrow + i * 32;
            uint32_t sa = bbase + row * 128 + ((ldcc ^ (row & 7)) << 4);
            const void* g = B + (size_t)(bn + row) * K + k0 + ldcc * 8;
            asm volatile("cp.async.cg.shared.global [%0], [%1], 16;"
                         :: "r"(sa), "l"(g));
        }
    };

    load_stage(0);
    asm volatile("cp.async.commit_group;");

    const int lr  = lane & 7;
    const int sub = lane >> 3;

    for (int t = 0; t < T; ++t) {
        if (t + 1 < T) load_stage(t + 1);
        asm volatile("cp.async.commit_group;");
        asm volatile("cp.async.wait_group 1;");
        __syncthreads();

        const int s = t & 1;
        const uint32_t abase = smbase + s * STG_B;
        const uint32_t bbase = abase + ASTG_B;

#pragma unroll
        for (int k16 = 0; k16 < 4; k16++) {
            uint32_t af[4][4];
            uint32_t bf[4][2];
#pragma unroll
            for (int mt = 0; mt < 4; mt++) {
                int row = wm * 64 + mt * 16 + lr + (sub & 1) * 8;
                int ch  = k16 * 2 + (sub >> 1);
                uint32_t ad = abase + row * 128 + ((ch ^ (row & 7)) << 4);
                asm volatile(
                    "ldmatrix.sync.aligned.m8n8.x4.shared.b16 {%0,%1,%2,%3}, [%4];"
                    : "=r"(af[mt][0]), "=r"(af[mt][1]),
                      "=r"(af[mt][2]), "=r"(af[mt][3]) : "r"(ad));
            }
#pragma unroll
            for (int np = 0; np < 2; np++) {
                int row = wn * 32 + np * 16 + lr + (sub >> 1) * 8;
                int ch  = k16 * 2 + (sub & 1);
                uint32_t bd = bbase + row * 128 + ((ch ^ (row & 7)) << 4);
                asm volatile(
                    "ldmatrix.sync.aligned.m8n8.x4.shared.b16 {%0,%1,%2,%3}, [%4];"
                    : "=r"(bf[np * 2][0]), "=r"(bf[np * 2][1]),
                      "=r"(bf[np * 2 + 1][0]), "=r"(bf[np * 2 + 1][1]) : "r"(bd));
            }
#pragma unroll
            for (int mt = 0; mt < 4; mt++)
#pragma unroll
                for (int nt = 0; nt < 4; nt++)
                    asm volatile(
                        "mma.sync.aligned.m16n8k16.row.col.f32.f16.f16.f32 "
                        "{%0,%1,%2,%3}, {%4,%5,%6,%7}, {%8,%9}, {%0,%1,%2,%3};"
                        : "+f"(acc[mt][nt][0]), "+f"(acc[mt][nt][1]),
                          "+f"(acc[mt][nt][2]), "+f"(acc[mt][nt][3])
                        : "r"(af[mt][0]), "r"(af[mt][1]),
                          "r"(af[mt][2]), "r"(af[mt][3]),
                          "r"(bf[nt][0]), "r"(bf[nt][1]));
        }
        __syncthreads();
    }

    const int crow0 = bm + wm * 64 + (lane >> 2);
    const int ccol0 = bn + wn * 32 + (lane & 3) * 2;
#pragma unroll
    for (int mt = 0; mt < 4; mt++) {
#pragma unroll
        for (int nt = 0; nt < 4; nt++) {
            float* p0 = C + (size_t)(crow0 + mt * 16) * Ntot + ccol0 + nt * 8;
            float* p1 = p0 + (size_t)8 * Ntot;
            *(float2*)p0 = make_float2(acc[mt][nt][0], acc[mt][nt][1]);
            *(float2*)p1 = make_float2(acc[mt][nt][2], acc[mt][nt][3]);
        }
    }
}

// ---------------- fp16 2-pass GEMM -> fp16 C (gate path) --------------------------
__global__ __launch_bounds__(256, 2) void gemm_hmma2h_hc(
    const __half* __restrict__ Ah, const __half* __restrict__ Al,
    const __half* __restrict__ B,
    __half* __restrict__ C, int Ntot, int K)
{
    extern __shared__ char smraw[];
    const int tid  = threadIdx.x;
    const int lane = tid & 31;
    const int wid  = tid >> 5;
    const int wm   = wid & 1;
    const int wn   = wid >> 1;
    const int bm   = blockIdx.y * BMt;
    const int bn   = blockIdx.x * BNt;

    const uint32_t smbase = smu32(smraw);
    const int ldrow = tid >> 3;
    const int ldcc  = tid & 7;

    const int TSEG = K >> 6;
    const int T = 2 * TSEG;

    float acc[4][4][4];
#pragma unroll
    for (int a = 0; a < 4; a++)
#pragma unroll
        for (int b = 0; b < 4; b++)
#pragma unroll
            for (int c = 0; c < 4; c++) acc[a][b][c] = 0.f;

    auto load_stage = [&](int t) {
        const int s = t & 1;
        const int seg = t / TSEG;
        const int k0 = (t - seg * TSEG) * BKt;
        const __half* Ag = seg ? Al : Ah;
        const uint32_t abase = smbase + s * STG_B;
        const uint32_t bbase = abase + ASTG_B;
#pragma unroll
        for (int i = 0; i < 4; i++) {
            int row = ldrow + i * 32;
            uint32_t sa = abase + row * 128 + ((ldcc ^ (row & 7)) << 4);
            const void* g = Ag + (size_t)(bm + row) * K + k0 + ldcc * 8;
            asm volatile("cp.async.cg.shared.global [%0], [%1], 16;"
                         :: "r"(sa), "l"(g));
        }
#pragma unroll
        for (int i = 0; i < 4; i++) {
            int row = ldrow + i * 32;
            uint32_t sa = bbase + row * 128 + ((ldcc ^ (row & 7)) << 4);
            const void* g = B + (size_t)(bn + row) * K + k0 + ldcc * 8;
            asm volatile("cp.async.cg.shared.global [%0], [%1], 16;"
                         :: "r"(sa), "l"(g));
        }
    };

    load_stage(0);
    asm volatile("cp.async.commit_group;");

    const int lr  = lane & 7;
    const int sub = lane >> 3;

    for (int t = 0; t < T; ++t) {
        if (t + 1 < T) load_stage(t + 1);
        asm volatile("cp.async.commit_group;");
        asm volatile("cp.async.wait_group 1;");
        __syncthreads();

        const int s = t & 1;
        const uint32_t abase = smbase + s * STG_B;
        const uint32_t bbase = abase + ASTG_B;

#pragma unroll
        for (int k16 = 0; k16 < 4; k16++) {
            uint32_t af[4][4];
            uint32_t bf[4][2];
#pragma unroll
            for (int mt = 0; mt < 4; mt++) {
                int row = wm * 64 + mt * 16 + lr + (sub & 1) * 8;
                int ch  = k16 * 2 + (sub >> 1);
                uint32_t ad = abase + row * 128 + ((ch ^ (row & 7)) << 4);
                asm volatile(
                    "ldmatrix.sync.aligned.m8n8.x4.shared.b16 {%0,%1,%2,%3}, [%4];"
                    : "=r"(af[mt][0]), "=r"(af[mt][1]),
                      "=r"(af[mt][2]), "=r"(af[mt][3]) : "r"(ad));
            }
#pragma unroll
            for (int np = 0; np < 2; np++) {
                int row = wn * 32 + np * 16 + lr + (sub >> 1) * 8;
                int ch  = k16 * 2 + (sub & 1);
                uint32_t bd = bbase + row * 128 + ((ch ^ (row & 7)) << 4);
                asm volatile(
                    "ldmatrix.sync.aligned.m8n8.x4.shared.b16 {%0,%1,%2,%3}, [%4];"
                    : "=r"(bf[np * 2][0]), "=r"(bf[np * 2][1]),
                      "=r"(bf[np * 2 + 1][0]), "=r"(bf[np * 2 + 1][1]) : "r"(bd));
            }
#pragma unroll
            for (int mt = 0; mt < 4; mt++)
#pragma unroll
                for (int nt = 0; nt < 4; nt++)
                    asm volatile(
                        "mma.sync.aligned.m16n8k16.row.col.f32.f16.f16.f32 "
                        "{%0,%1,%2,%3}, {%4,%5,%6,%7}, {%8,%9}, {%0,%1,%2,%3};"
                        : "+f"(acc[mt][nt][0]), "+f"(acc[mt][nt][1]),
                          "+f"(acc[mt][nt][2]), "+f"(acc[mt][nt][3])
                        : "r"(af[mt][0]), "r"(af[mt][1]),
                          "r"(af[mt][2]), "r"(af[mt][3]),
                          "r"(bf[nt][0]), "r"(bf[nt][1]));
        }
        __syncthreads();
    }

    const int crow0 = bm + wm * 64 + (lane >> 2);
    const int ccol0 = bn + wn * 32 + (lane & 3) * 2;
#pragma unroll
    for (int mt = 0; mt < 4; mt++) {
#pragma unroll
        for (int nt = 0; nt < 4; nt++) {
            __half* p0 = C + (size_t)(crow0 + mt * 16) * Ntot + ccol0 + nt * 8;
            __half* p1 = p0 + (size_t)8 * Ntot;
            __half2 a(__float2half_rn(acc[mt][nt][0]), __float2half_rn(acc[mt][nt][1]));
            __half2 b(__float2half_rn(acc[mt][nt][2]), __float2half_rn(acc[mt][nt][3]));
            *(uint32_t*)p0 = *(uint32_t*)&a;
            *(uint32_t*)p1 = *(uint32_t*)&b;
        }
    }
}

// ---------------- RoPE tables (double precision, once) ----------------------------
__global__ void rope_table_kernel()
{
    int idx = blockIdx.x * 256 + threadIdx.x;
    int l = idx >> 6, j = idx & 63;
    double invf = exp(-((double)(2 * j) / 128.0) * log(10000.0));
    double ang = (double)l * invf;
    g_ctab[idx] = (float)cos(ang);
    g_stab[idx] = (float)sin(ang);
}

// ---------------- dt = softplus(hs @ Win^T + bias), W-tiled -----------------------
__global__ __launch_bounds__(128) void dt_kernel(
    const float* __restrict__ hs, const float* __restrict__ Win,
    const float* __restrict__ dtb)
{
    __shared__ float Wt[NH][132];
    const int row = blockIdx.x * 128 + threadIdx.x;
    const int tid = threadIdx.x;
    float acc[NH];
#pragma unroll
    for (int h = 0; h < NH; h++) acc[h] = 0.f;

    for (int k0 = 0; k0 < HIDDEN; k0 += 128) {
        __syncthreads();
        for (int t = tid; t < NH * 32; t += 128) {
            int h = t >> 5, kq = (t & 31) * 4;
            float4 w = *(const float4*)&Win[(size_t)h * HIDDEN + k0 + kq];
            *(float4*)&Wt[h][kq] = w;
        }
        __syncthreads();
        const float* hrow = hs + (size_t)row * HIDDEN + k0;
        for (int kk = 0; kk < 128; kk += 4) {
            float4 x = *(const float4*)(hrow + kk);
#pragma unroll
            for (int h = 0; h < NH; h++) {
                float4 w = *(const float4*)&Wt[h][kk];
                acc[h] += x.x * w.x + x.y * w.y + x.z * w.z + x.w * w.w;
            }
        }
    }
#pragma unroll
    for (int h = 0; h < NH; h++) {
        float s = acc[h] + dtb[h];
        float sp = fmaxf(s, 0.f) + log1pf(expf(-fabsf(s)));
        g_dt[(size_t)row * NH + h] = sp;
    }
}

// ---------------- per-chunk cumulative gate G -------------------------------------
__global__ void cumsum_kernel(const float* __restrict__ Alog)
{
    __shared__ float smv[CHUNK];
    int n = blockIdx.x, h = blockIdx.y, i = threadIdx.x;
    float A = -expf(Alog[h]);
    smv[i] = g_dt[(size_t)(n * CHUNK + i) * NH + h] * A;
    __syncthreads();
    for (int off = 1; off < CHUNK; off <<= 1) {
        float t = (i >= off) ? smv[i - off] : 0.f;
        __syncthreads();
        smv[i] += t;
        __syncthreads();
    }
    g_G[(size_t)h * LSEQ + n * CHUNK + i] = smv[i];
}

// ---------------- kernel A: decayed scores Sd[j][i] (fp16) + chunk states ---------
__global__ __launch_bounds__(256) void chunk_intra_kernel()
{
    extern __shared__ float sm[];
    float* U = sm;
    float* V = sm + 128 * PADA;
    __shared__ float Gsm[CHUNK];
    __shared__ float dsm[CHUNK];

    const int n = blockIdx.x, h = blockIdx.y;
    const int tid = threadIdx.x;
    const int tcol = tid & 15, trow = tid >> 4;
    const int lrow = tid >> 5;
    const int lane4 = (tid & 31) * 4;
    const int kvb = (h >> 2) * DH;

    if (tid < CHUNK) {
        Gsm[tid] = g_G[(size_t)h * LSEQ + n * CHUNK + tid];
        dsm[tid] = g_dt[(size_t)(n * CHUNK + tid) * NH + h];
    }
    for (int p = 0; p < 16; p++) {
        int i = p * 8 + lrow;
        float4 qv = *(const float4*)&g_q[(size_t)(n * CHUNK + i) * QDIM + h * DH + lane4];
        U[(lane4 + 0) * PADA + i] = qv.x; U[(lane4 + 1) * PADA + i] = qv.y;
        U[(lane4 + 2) * PADA + i] = qv.z; U[(lane4 + 3) * PADA + i] = qv.w;
        float4 kv = *(const float4*)&g_k[(size_t)(n * CHUNK + i) * KVDIM + kvb + lane4];
        V[(lane4 + 0) * PADA + i] = kv.x; V[(lane4 + 1) * PADA + i] = kv.y;
        V[(lane4 + 2) * PADA + i] = kv.z; V[(lane4 + 3) * PADA + i] = kv.w;
    }
    __syncthreads();

    float acc[8][8];
#pragma unroll
    for (int r = 0; r < 8; r++)
#pragma unroll
        for (int c = 0; c < 8; c++) acc[r][c] = 0.f;

#pragma unroll 4
    for (int kk = 0; kk < 128; kk++) {
        float a[8], b[8];
#pragma unroll
        for (int r = 0; r < 8; r++) a[r] = V[kk * PADA + trow * 8 + r];
#pragma unroll
        for (int c = 0; c < 8; c++) b[c] = U[kk * PADA + tcol * 8 + c];
#pragma unroll
        for (int r = 0; r < 8; r++)
#pragma unroll
            for (int c = 0; c < 8; c++) acc[r][c] += a[r] * b[c];
    }
    const size_t off = ((size_t)h * NCHUNK + n) * (CHUNK * CHUNK);
#pragma unroll
    for (int r = 0; r < 8; r++) {
        int j = trow * 8 + r;
        float Gj = Gsm[j];
        float vv[8];
#pragma unroll
        for (int c = 0; c < 8; c++) {
            int i = tcol * 8 + c;
            vv[c] = (i >= j) ? acc[r][c] * expf(Gsm[i] - Gj) : 0.f;
        }
        __half2 p0(__float2half_rn(vv[0]), __float2half_rn(vv[1]));
        __half2 p1(__float2half_rn(vv[2]), __float2half_rn(vv[3]));
        __half2 p2(__float2half_rn(vv[4]), __float2half_rn(vv[5]));
        __half2 p3(__float2half_rn(vv[6]), __float2half_rn(vv[7]));
        uint4 pk;
        pk.x = *(uint32_t*)&p0; pk.y = *(uint32_t*)&p1;
        pk.z = *(uint32_t*)&p2; pk.w = *(uint32_t*)&p3;
        *(uint4*)&g_S[off + (size_t)j * CHUNK + tcol * 8] = pk;
    }
    __syncthreads();

    float Glast = Gsm[CHUNK - 1];
    for (int p = 0; p < 16; p++) {
        int j = p * 8 + lrow;
        float w = expf(Glast - Gsm[j]);
        float dt = dsm[j];
        float4 kv = *(const float4*)&g_k[(size_t)(n * CHUNK + j) * KVDIM + kvb + lane4];
        V[j * PADA + lane4 + 0] = kv.x * w; V[j * PADA + lane4 + 1] = kv.y * w;
        V[j * PADA + lane4 + 2] = kv.z * w; V[j * PADA + lane4 + 3] = kv.w * w;
        float4 vv = *(const float4*)&g_v[(size_t)(n * CHUNK + j) * KVDIM + kvb + lane4];
        U[j * PADA + lane4 + 0] = vv.x * dt; U[j * PADA + lane4 + 1] = vv.y * dt;
        U[j * PADA + lane4 + 2] = vv.z * dt; U[j * PADA + lane4 + 3] = vv.w * dt;
    }
    __syncthreads();

    float acc2[8][8];
#pragma unroll
    for (int r = 0; r < 8; r++)
#pragma unroll
        for (int c = 0; c < 8; c++) acc2[r][c] = 0.f;

#pragma unroll 4
    for (int kk = 0; kk < 128; kk++) {
        float a[8], b[8];
#pragma unroll
        for (int r = 0; r < 8; r++) a[r] = V[kk * PADA + trow * 8 + r];
#pragma unroll
        for (int c = 0; c < 8; c++) b[c] = U[kk * PADA + tcol * 8 + c];
#pragma unroll
        for (int r = 0; r < 8; r++)
#pragma unroll
            for (int c = 0; c < 8; c++) acc2[r][c] += a[r] * b[c];
    }
    const size_t off2 = ((size_t)h * NCHUNK + n) * (DH * DH);
#pragma unroll
    for (int r = 0; r < 8; r++) {
        int d = trow * 8 + r;
#pragma unroll
        for (int c = 0; c < 8; c++)
            g_cs[off2 + (size_t)d * DH + tcol * 8 + c] = acc2[r][c];
    }
}

// ---------------- inter-chunk recurrent scan --------------------------------------
__global__ void scan_kernel()
{
    int h = blockIdx.y;
    size_t base = (size_t)blockIdx.x * 1024 + threadIdx.x * 4;
    float4 s = make_float4(0.f, 0.f, 0.f, 0.f);
    for (int nn = 0; nn < NCHUNK; nn++) {
        size_t o = ((size_t)h * NCHUNK + nn) * (DH * DH) + base;
        *(float4*)&g_prev[o] = s;
        float dec = expf(g_G[(size_t)h * LSEQ + nn * CHUNK + CHUNK - 1]);
        float4 cs = *(const float4*)&g_cs[o];
        s.x = s.x * dec + cs.x; s.y = s.y * dec + cs.y;
        s.z = s.z * dec + cs.z; s.w = s.w * dec + cs.w;
    }
}

// ---------------- kernel B: y_intra + y_inter + RMS + SiLU gate -> fp16 split -----
__global__ __launch_bounds__(256) void chunk_out_kernel(const float* __restrict__ gnw)
{
    extern __shared__ float sm[];
    float* V = sm;
    float* U = sm + 128 * PADA;
    __shared__ float Gsm[CHUNK];
    __shared__ float dsm[CHUNK];
    __shared__ float red[256];
    __shared__ float rinv[CHUNK];

    const int n = blockIdx.x, h = blockIdx.y;
    const int tid = threadIdx.x;
    const int tcol = tid & 15, trow = tid >> 4;
    const int lrow = tid >> 5;
    const int lane4 = (tid & 31) * 4;
    const int kvb = (h >> 2) * DH;
    const size_t offS = ((size_t)h * NCHUNK + n) * (CHUNK * CHUNK);
    const size_t off  = ((size_t)h * NCHUNK + n) * (DH * DH);

    if (tid < CHUNK) {
        Gsm[tid] = g_G[(size_t)h * LSEQ + n * CHUNK + tid];
        dsm[tid] = g_dt[(size_t)(n * CHUNK + tid) * NH + h];
    }
    for (int t = tid * 8; t < CHUNK * CHUNK; t += 2048) {
        uint4 sv = *(const uint4*)&g_S[offS + t];
        int j = t >> 7, i = t & 127;
        __half2* hp = (__half2*)&sv;
        float2 f0 = __half22float2(hp[0]);
        float2 f1 = __half22float2(hp[1]);
        float2 f2 = __half22float2(hp[2]);
        float2 f3 = __half22float2(hp[3]);
        V[j * PADA + i + 0] = f0.x; V[j * PADA + i + 1] = f0.y;
        V[j * PADA + i + 2] = f1.x; V[j * PADA + i + 3] = f1.y;
        V[j * PADA + i + 4] = f2.x; V[j * PADA + i + 5] = f2.y;
        V[j * PADA + i + 6] = f3.x; V[j * PADA + i + 7] = f3.y;
    }
    __syncthreads();
    for (int p = 0; p < 16; p++) {
        int j = p * 8 + lrow;
        float dt = dsm[j];
        float4 vv = *(const float4*)&g_v[(size_t)(n * CHUNK + j) * KVDIM + kvb + lane4];
        U[j * PADA + lane4 + 0] = vv.x * dt; U[j * PADA + lane4 + 1] = vv.y * dt;
        U[j * PADA + lane4 + 2] = vv.z * dt; U[j * PADA + lane4 + 3] = vv.w * dt;
    }
    __syncthreads();

    float acc[8][8];
#pragma unroll
    for (int r = 0; r < 8; r++)
#pragma unroll
        for (int c = 0; c < 8; c++) acc[r][c] = 0.f;

#pragma unroll 4
    for (int kk = 0; kk < 128; kk++) {
        float a[8], b[8];
#pragma unroll
        for (int r = 0; r < 8; r++) a[r] = V[kk * PADA + trow * 8 + r];
#pragma unroll
        for (int c = 0; c < 8; c++) b[c] = U[kk * PADA + tcol * 8 + c];
#pragma unroll
        for (int r = 0; r < 8; r++)
#pragma unroll
            for (int c = 0; c < 8; c++) acc[r][c] += a[r] * b[c];
    }
    __syncthreads();

    for (int p = 0; p < 16; p++) {
        int i = p * 8 + lrow;
        float eg = expf(Gsm[i]);
        float4 qv = *(const float4*)&g_q[(size_t)(n * CHUNK + i) * QDIM + h * DH + lane4];
        V[(lane4 + 0) * PADA + i] = qv.x * eg; V[(lane4 + 1) * PADA + i] = qv.y * eg;
        V[(lane4 + 2) * PADA + i] = qv.z * eg; V[(lane4 + 3) * PADA + i] = qv.w * eg;
    }
    for (int t = tid * 4; t < DH * DH; t += 1024) {
        float4 pv = *(const float4*)&g_prev[off + t];
        int d = t >> 7, e = t & 127;
        U[d * PADA + e + 0] = pv.x; U[d * PADA + e + 1] = pv.y;
        U[d * PADA + e + 2] = pv.z; U[d * PADA + e + 3] = pv.w;
    }
    __syncthreads();

#pragma unroll 4
    for (int kk = 0; kk < 128; kk++) {
        float a[8], b[8];
#pragma unroll
        for (int r = 0; r < 8; r++) a[r] = V[kk * PADA + trow * 8 + r];
#pragma unroll
        for (int c = 0; c < 8; c++) b[c] = U[kk * PADA + tcol * 8 + c];
#pragma unroll
        for (int r = 0; r < 8; r++)
#pragma unroll
            for (int c = 0; c < 8; c++) acc[r][c] += a[r] * b[c];
    }
    __syncthreads();

#pragma unroll
    for (int r = 0; r < 8; r++)
#pragma unroll
        for (int c = 0; c < 8; c++)
            V[(trow * 8 + r) * PADA + tcol * 8 + c] = acc[r][c];
    __syncthreads();

    {
        int row = tid >> 1, half = tid & 1;
        float ss = 0.f;
        for (int e = half * 64; e < half * 64 + 64; e++) {
            float v = V[row * PADA + e];
            ss += v * v;
        }
        red[tid] = ss;
    }
    __syncthreads();
    if (tid < CHUNK)
        rinv[tid] = rsqrtf((red[tid * 2] + red[tid * 2 + 1]) * (1.0f / DH) + 1e-5f);
    __syncthreads();

    for (int t = tid * 2; t < CHUNK * DH; t += 512) {
        int i = t >> 7, e = t & 127;
        int l = n * CHUNK + i;
        float ri = rinv[i];
        float v0 = V[i * PADA + e + 0] * ri * gnw[e + 0];
        float v1 = V[i * PADA + e + 1] * ri * gnw[e + 1];
        uint32_t gu = *(const uint32_t*)&g_gateh[(size_t)l * QDIM + h * DH + e];
        float2 gt = __half22float2(*(__half2*)&gu);
        v0 *= gt.x / (1.f + expf(-gt.x));
        v1 *= gt.y / (1.f + expf(-gt.y));
        __half h0 = __float2half_rn(v0);
        __half h1 = __float2half_rn(v1);
        __half l0 = __float2half_rn(v0 - __half2float(h0));
        __half l1 = __float2half_rn(v1 - __half2float(h1));
        __half2 hp(h0, h1), lp(l0, l1);
        *(uint32_t*)&g_yfh[(size_t)l * QDIM + h * DH + e] = *(uint32_t*)&hp;
        *(uint32_t*)&g_yfl[(size_t)l * QDIM + h * DH + e] = *(uint32_t*)&lp;
    }
}

// ---------------- launch -----------------------------------------------------------
extern "C" void kernel_launch(void* const* d_in, const int* in_sizes, int n_in,
                              void* d_out, int out_size)
{
    const float* hs   = (const float*)d_in[0];
    const float* Wq   = (const float*)d_in[1];
    const float* Wk   = (const float*)d_in[2];
    const float* Wv   = (const float*)d_in[3];
    const float* Wo   = (const float*)d_in[4];
    const float* Wg   = (const float*)d_in[5];
    const float* Win  = (const float*)d_in[6];
    const float* dtb  = (const float*)d_in[7];
    const float* Alog = (const float*)d_in[8];
    const float* gnw  = (const float*)d_in[9];
    float* out = (float*)d_out;

    float *q, *k, *v;
    cudaGetSymbolAddress((void**)&q, g_q);
    cudaGetSymbolAddress((void**)&k, g_k);
    cudaGetSymbolAddress((void**)&v, g_v);
    __half* gateh;
    cudaGetSymbolAddress((void**)&gateh, g_gateh);

    __nv_bfloat16 *hsh, *hsl, *Wqh, *Wql, *Wkh, *Wkl, *Wvh, *Wvl;
    cudaGetSymbolAddress((void**)&hsh, g_hsh);  cudaGetSymbolAddress((void**)&hsl, g_hsl);
    cudaGetSymbolAddress((void**)&Wqh, g_Wqh);  cudaGetSymbolAddress((void**)&Wql, g_Wql);
    cudaGetSymbolAddress((void**)&Wkh, g_Wkh);  cudaGetSymbolAddress((void**)&Wkl, g_Wkl);
    cudaGetSymbolAddress((void**)&Wvh, g_Wvh);  cudaGetSymbolAddress((void**)&Wvl, g_Wvl);

    __half *hsfh, *hsfl, *Wgc, *Woc, *yfh, *yfl;
    cudaGetSymbolAddress((void**)&hsfh, g_hsfh);
    cudaGetSymbolAddress((void**)&hsfl, g_hsfl);
    cudaGetSymbolAddress((void**)&Wgc, g_Wgc);
    cudaGetSymbolAddress((void**)&Woc, g_Woc);
    cudaGetSymbolAddress((void**)&yfh, g_yfh);
    cudaGetSymbolAddress((void**)&yfl, g_yfl);

    const int SMEM_AB = 2 * 128 * PADA * (int)sizeof(float);
    cudaFuncSetAttribute(chunk_intra_kernel,
                         cudaFuncAttributeMaxDynamicSharedMemorySize, SMEM_AB);
    cudaFuncSetAttribute(chunk_out_kernel,
                         cudaFuncAttributeMaxDynamicSharedMemorySize, SMEM_AB);
    cudaFuncSetAttribute(gemm_hmma3_t<0>,
                         cudaFuncAttributeMaxDynamicSharedMemorySize, GEMM_SMEM);
    cudaFuncSetAttribute(gemm_hmma3_t<1>,
                         cudaFuncAttributeMaxDynamicSharedMemorySize, GEMM_SMEM_ROPE);
    cudaFuncSetAttribute(gemm_hmma2h,
                         cudaFuncAttributeMaxDynamicSharedMemorySize, GEMM_SMEM);
    cudaFuncSetAttribute(gemm_hmma2h_hc,
                         cudaFuncAttributeMaxDynamicSharedMemorySize, GEMM_SMEM);

    const size_t NBIG = (size_t)HIDDEN * HIDDEN;      // 16M
    const size_t NSML = (size_t)KVDIM * HIDDEN;       // 4M

    rope_table_kernel<<<(LSEQ * 64) / 256, 256>>>();
    cvt_hs_all<<<(int)(NBIG / 1024), 256>>>(hs);
    cvt_split<<<(int)(NBIG / 1024), 256>>>(Wq, Wqh, Wql, NBIG);
    cvt_split<<<(int)(NSML / 1024), 256>>>(Wk, Wkh, Wkl, NSML);
    cvt_split<<<(int)(NSML / 1024), 256>>>(Wv, Wvh, Wvl, NSML);
    cvt_h<<<(int)(NBIG / 1024), 256>>>(Wg, Wgc, NBIG);
    gemm_hmma3_t<1><<<dim3(QDIM / BNt, LSEQ / BMt),  256, GEMM_SMEM_ROPE>>>(hsh, hsl, Wqh, Wql, q, QDIM,  HIDDEN);
    gemm_hmma3_t<1><<<dim3(KVDIM / BNt, LSEQ / BMt), 256, GEMM_SMEM_ROPE>>>(hsh, hsl, Wkh, Wkl, k, KVDIM, HIDDEN);
    gemm_hmma3_t<0><<<dim3(KVDIM / BNt, LSEQ / BMt), 256, GEMM_SMEM>>>(hsh, hsl, Wvh, Wvl, v, KVDIM, HIDDEN);
    gemm_hmma2h_hc<<<dim3(QDIM / BNt, LSEQ / BMt), 256, GEMM_SMEM>>>(hsfh, hsfl, Wgc, gateh, QDIM, HIDDEN);

    dt_kernel<<<LSEQ / 128, 128>>>(hs, Win, dtb);
    cumsum_kernel<<<dim3(NCHUNK, NH), CHUNK>>>(Alog);
    chunk_intra_kernel<<<dim3(NCHUNK, NH), 256, SMEM_AB>>>();
    scan_kernel<<<dim3(16, NH), 256>>>();
    chunk_out_kernel<<<dim3(NCHUNK, NH), 256, SMEM_AB>>>(gnw);

    cvt_h<<<(int)(NBIG / 1024), 256>>>(Wo, Woc, NBIG);
    gemm_hmma2h<<<dim3(HIDDEN / BNt, LSEQ / BMt), 256, GEMM_SMEM>>>(yfh, yfl, Woc, out, HIDDEN, HIDDEN);
}

// round 17
// speedup vs baseline: 1.5115x; 1.5115x over previous
#include <cuda_runtime.h>
#include <cuda_bf16.h>
#include <cuda_fp16.h>
#include <math.h>
#include <stdint.h>

#define LSEQ 4096
#define HIDDEN 4096
#define NH 32
#define NKV 8
#define DH 128
#define CHUNK 128
#define NCHUNK 32
#define QDIM 4096
#define KVDIM 1024
#define PADA 130

// ---------------- scratch (device globals: no allocations allowed) ----------------
__device__ float g_q[(size_t)LSEQ * QDIM];
__device__ float g_k[(size_t)LSEQ * KVDIM];
__device__ float g_v[(size_t)LSEQ * KVDIM];
__device__ __half g_gateh[(size_t)LSEQ * QDIM];
__device__ float g_dt[(size_t)LSEQ * NH];
__device__ float g_G[(size_t)NH * LSEQ];
__device__ __half g_S[(size_t)NH * NCHUNK * CHUNK * CHUNK];
__device__ float g_cs[(size_t)NH * NCHUNK * DH * DH];
__device__ float g_prev[(size_t)NH * NCHUNK * DH * DH];
__device__ float g_ctab[LSEQ * 64];
__device__ float g_stab[LSEQ * 64];

// bf16 hi/lo split operands (Q/K/V path)
__device__ __nv_bfloat16 g_hsh[(size_t)LSEQ * HIDDEN];
__device__ __nv_bfloat16 g_hsl[(size_t)LSEQ * HIDDEN];
__device__ __nv_bfloat16 g_Wqh[(size_t)QDIM * HIDDEN];
__device__ __nv_bfloat16 g_Wql[(size_t)QDIM * HIDDEN];
__device__ __nv_bfloat16 g_Wkh[(size_t)KVDIM * HIDDEN];
__device__ __nv_bfloat16 g_Wkl[(size_t)KVDIM * HIDDEN];
__device__ __nv_bfloat16 g_Wvh[(size_t)KVDIM * HIDDEN];
__device__ __nv_bfloat16 g_Wvl[(size_t)KVDIM * HIDDEN];

// fp16 operands (gate / output path)
__device__ __half g_hsfh[(size_t)LSEQ * HIDDEN];
__device__ __half g_hsfl[(size_t)LSEQ * HIDDEN];
__device__ __half g_Wgc[(size_t)QDIM * HIDDEN];
__device__ __half g_Woc[(size_t)HIDDEN * QDIM];
__device__ __half g_yfh[(size_t)LSEQ * QDIM];
__device__ __half g_yfl[(size_t)LSEQ * QDIM];

__device__ __forceinline__ uint32_t smu32(const void* p) {
    return (uint32_t)__cvta_generic_to_shared(p);
}

// ---------------- merged hs converter: one read -> bf16 split + fp16 split --------
__global__ void cvt_hs_all(const float* __restrict__ x)
{
    size_t i = ((size_t)blockIdx.x * 256 + threadIdx.x) * 4;
    float4 v = *(const float4*)(x + i);

    __nv_bfloat16 bh0 = __float2bfloat16(v.x);
    __nv_bfloat16 bh1 = __float2bfloat16(v.y);
    __nv_bfloat16 bh2 = __float2bfloat16(v.z);
    __nv_bfloat16 bh3 = __float2bfloat16(v.w);
    __nv_bfloat16 bl0 = __float2bfloat16(v.x - __bfloat162float(bh0));
    __nv_bfloat16 bl1 = __float2bfloat16(v.y - __bfloat162float(bh1));
    __nv_bfloat16 bl2 = __float2bfloat16(v.z - __bfloat162float(bh2));
    __nv_bfloat16 bl3 = __float2bfloat16(v.w - __bfloat162float(bh3));
    __nv_bfloat162 bp0(bh0, bh1), bp1(bh2, bh3), bq0(bl0, bl1), bq1(bl2, bl3);
    uint2 bu, bv;
    bu.x = *(uint32_t*)&bp0; bu.y = *(uint32_t*)&bp1;
    bv.x = *(uint32_t*)&bq0; bv.y = *(uint32_t*)&bq1;
    *(uint2*)(g_hsh + i) = bu;
    *(uint2*)(g_hsl + i) = bv;

    __half fh0 = __float2half_rn(v.x);
    __half fh1 = __float2half_rn(v.y);
    __half fh2 = __float2half_rn(v.z);
    __half fh3 = __float2half_rn(v.w);
    __half fl0 = __float2half_rn(v.x - __half2float(fh0));
    __half fl1 = __float2half_rn(v.y - __half2float(fh1));
    __half fl2 = __float2half_rn(v.z - __half2float(fh2));
    __half fl3 = __float2half_rn(v.w - __half2float(fh3));
    __half2 fp0(fh0, fh1), fp1(fh2, fh3), fq0(fl0, fl1), fq1(fl2, fl3);
    uint2 fu, fv;
    fu.x = *(uint32_t*)&fp0; fu.y = *(uint32_t*)&fp1;
    fv.x = *(uint32_t*)&fq0; fv.y = *(uint32_t*)&fq1;
    *(uint2*)(g_hsfh + i) = fu;
    *(uint2*)(g_hsfl + i) = fv;
}

// ---------------- fp32 -> (hi,lo) bf16 split --------------------------------------
__global__ void cvt_split(const float* __restrict__ x,
                          __nv_bfloat16* __restrict__ hi,
                          __nv_bfloat16* __restrict__ lo, size_t n)
{
    size_t i = ((size_t)blockIdx.x * 256 + threadIdx.x) * 4;
    if (i >= n) return;
    float4 v = *(const float4*)(x + i);
    __nv_bfloat16 h0 = __float2bfloat16(v.x);
    __nv_bfloat16 h1 = __float2bfloat16(v.y);
    __nv_bfloat16 h2 = __float2bfloat16(v.z);
    __nv_bfloat16 h3 = __float2bfloat16(v.w);
    __nv_bfloat16 l0 = __float2bfloat16(v.x - __bfloat162float(h0));
    __nv_bfloat16 l1 = __float2bfloat16(v.y - __bfloat162float(h1));
    __nv_bfloat16 l2 = __float2bfloat16(v.z - __bfloat162float(h2));
    __nv_bfloat16 l3 = __float2bfloat16(v.w - __bfloat162float(h3));
    __nv_bfloat162 hp0(h0, h1), hp1(h2, h3), lp0(l0, l1), lp1(l2, l3);
    uint2 hu, lu;
    hu.x = *(uint32_t*)&hp0; hu.y = *(uint32_t*)&hp1;
    lu.x = *(uint32_t*)&lp0; lu.y = *(uint32_t*)&lp1;
    *(uint2*)(hi + i) = hu;
    *(uint2*)(lo + i) = lu;
}

// ---------------- fp32 -> fp16 single ---------------------------------------------
__global__ void cvt_h(const float* __restrict__ x, __half* __restrict__ o, size_t n)
{
    size_t i = ((size_t)blockIdx.x * 256 + threadIdx.x) * 4;
    if (i >= n) return;
    float4 v = *(const float4*)(x + i);
    __half2 a = __floats2half2_rn(v.x, v.y);
    __half2 b = __floats2half2_rn(v.z, v.w);
    uint2 u;
    u.x = *(uint32_t*)&a; u.y = *(uint32_t*)&b;
    *(uint2*)(o + i) = u;
}

// ---------------- GEMM config (round-10 measured best: 8 warps, 64x32 tile) -------
#define BMt 128
#define BNt 128
#define BKt 64
#define ASTG_B (BMt * 128)
#define BSTG_B (BNt * 128)
#define STG_B  (ASTG_B + BSTG_B)      // 32768
#define GEMM_SMEM (2 * STG_B)         // 65536

// ---------------- bf16 3-pass GEMM: C = (Ah+Al) @ (Bh+Bl)^T (drop lo*lo) ----------
__global__ __launch_bounds__(256, 2) void gemm_hmma3(
    const __nv_bfloat16* __restrict__ Ah, const __nv_bfloat16* __restrict__ Al,
    const __nv_bfloat16* __restrict__ Bh, const __nv_bfloat16* __restrict__ Bl,
    float* __restrict__ C, int Ntot, int K)
{
    extern __shared__ char smraw[];
    const int tid  = threadIdx.x;
    const int lane = tid & 31;
    const int wid  = tid >> 5;
    const int wm   = wid & 1;
    const int wn   = wid >> 1;
    const int bm   = blockIdx.y * BMt;
    const int bn   = blockIdx.x * BNt;

    const uint32_t smbase = smu32(smraw);
    const int ldrow = tid >> 3;
    const int ldcc  = tid & 7;

    const int TSEG = K >> 6;
    const int T = 3 * TSEG;

    float acc[4][4][4];
#pragma unroll
    for (int a = 0; a < 4; a++)
#pragma unroll
        for (int b = 0; b < 4; b++)
#pragma unroll
            for (int c = 0; c < 4; c++) acc[a][b][c] = 0.f;

    auto load_stage = [&](int t) {
        const int s = t & 1;
        const int seg = t / TSEG;
        const int k0 = (t - seg * TSEG) * BKt;
        const __nv_bfloat16* Ag = (seg == 1) ? Al : Ah;
        const __nv_bfloat16* Bg = (seg == 2) ? Bl : Bh;
        const uint32_t abase = smbase + s * STG_B;
        const uint32_t bbase = abase + ASTG_B;
#pragma unroll
        for (int i = 0; i < 4; i++) {
            int row = ldrow + i * 32;
            uint32_t sa = abase + row * 128 + ((ldcc ^ (row & 7)) << 4);
            const void* g = Ag + (size_t)(bm + row) * K + k0 + ldcc * 8;
            asm volatile("cp.async.cg.shared.global [%0], [%1], 16;"
                         :: "r"(sa), "l"(g));
        }
#pragma unroll
        for (int i = 0; i < 4; i++) {
            int row = ldrow + i * 32;
            uint32_t sa = bbase + row * 128 + ((ldcc ^ (row & 7)) << 4);
            const void* g = Bg + (size_t)(bn + row) * K + k0 + ldcc * 8;
            asm volatile("cp.async.cg.shared.global [%0], [%1], 16;"
                         :: "r"(sa), "l"(g));
        }
    };

    load_stage(0);
    asm volatile("cp.async.commit_group;");

    const int lr  = lane & 7;
    const int sub = lane >> 3;

    for (int t = 0; t < T; ++t) {
        if (t + 1 < T) load_stage(t + 1);
        asm volatile("cp.async.commit_group;");
        asm volatile("cp.async.wait_group 1;");
        __syncthreads();

        const int s = t & 1;
        const uint32_t abase = smbase + s * STG_B;
        const uint32_t bbase = abase + ASTG_B;

#pragma unroll
        for (int k16 = 0; k16 < 4; k16++) {
            uint32_t af[4][4];
            uint32_t bf[4][2];
#pragma unroll
            for (int mt = 0; mt < 4; mt++) {
                int row = wm * 64 + mt * 16 + lr + (sub & 1) * 8;
                int ch  = k16 * 2 + (sub >> 1);
                uint32_t ad = abase + row * 128 + ((ch ^ (row & 7)) << 4);
                asm volatile(
                    "ldmatrix.sync.aligned.m8n8.x4.shared.b16 {%0,%1,%2,%3}, [%4];"
                    : "=r"(af[mt][0]), "=r"(af[mt][1]),
                      "=r"(af[mt][2]), "=r"(af[mt][3]) : "r"(ad));
            }
#pragma unroll
            for (int np = 0; np < 2; np++) {
                int row = wn * 32 + np * 16 + lr + (sub >> 1) * 8;
                int ch  = k16 * 2 + (sub & 1);
                uint32_t bd = bbase + row * 128 + ((ch ^ (row & 7)) << 4);
                asm volatile(
                    "ldmatrix.sync.aligned.m8n8.x4.shared.b16 {%0,%1,%2,%3}, [%4];"
                    : "=r"(bf[np * 2][0]), "=r"(bf[np * 2][1]),
                      "=r"(bf[np * 2 + 1][0]), "=r"(bf[np * 2 + 1][1]) : "r"(bd));
            }
#pragma unroll
            for (int mt = 0; mt < 4; mt++)
#pragma unroll
                for (int nt = 0; nt < 4; nt++)
                    asm volatile(
                        "mma.sync.aligned.m16n8k16.row.col.f32.bf16.bf16.f32 "
                        "{%0,%1,%2,%3}, {%4,%5,%6,%7}, {%8,%9}, {%0,%1,%2,%3};"
                        : "+f"(acc[mt][nt][0]), "+f"(acc[mt][nt][1]),
                          "+f"(acc[mt][nt][2]), "+f"(acc[mt][nt][3])
                        : "r"(af[mt][0]), "r"(af[mt][1]),
                          "r"(af[mt][2]), "r"(af[mt][3]),
                          "r"(bf[nt][0]), "r"(bf[nt][1]));
        }
        __syncthreads();
    }

    const int crow0 = bm + wm * 64 + (lane >> 2);
    const int ccol0 = bn + wn * 32 + (lane & 3) * 2;
#pragma unroll
    for (int mt = 0; mt < 4; mt++) {
#pragma unroll
        for (int nt = 0; nt < 4; nt++) {
            float* p0 = C + (size_t)(crow0 + mt * 16) * Ntot + ccol0 + nt * 8;
            float* p1 = p0 + (size_t)8 * Ntot;
            *(float2*)p0 = make_float2(acc[mt][nt][0], acc[mt][nt][1]);
            *(float2*)p1 = make_float2(acc[mt][nt][2], acc[mt][nt][3]);
        }
    }
}

// ---------------- fp16 2-pass GEMM -> fp32 C (output path) ------------------------
__global__ __launch_bounds__(256, 2) void gemm_hmma2h(
    const __half* __restrict__ Ah, const __half* __restrict__ Al,
    const __half* __restrict__ B,
    float* __restrict__ C, int Ntot, int K)
{
    extern __shared__ char smraw[];
    const int tid  = threadIdx.x;
    const int lane = tid & 31;
    const int wid  = tid >> 5;
    const int wm   = wid & 1;
    const int wn   = wid >> 1;
    const int bm   = blockIdx.y * BMt;
    const int bn   = blockIdx.x * BNt;

    const uint32_t smbase = smu32(smraw);
    const int ldrow = tid >> 3;
    const int ldcc  = tid & 7;

    const int TSEG = K >> 6;
    const int T = 2 * TSEG;

    float acc[4][4][4];
#pragma unroll
    for (int a = 0; a < 4; a++)
#pragma unroll
        for (int b = 0; b < 4; b++)
#pragma unroll
            for (int c = 0; c < 4; c++) acc[a][b][c] = 0.f;

    auto load_stage = [&](int t) {
        const int s = t & 1;
        const int seg = t / TSEG;
        const int k0 = (t - seg * TSEG) * BKt;
        const __half* Ag = seg ? Al : Ah;
        const uint32_t abase = smbase + s * STG_B;
        const uint32_t bbase = abase + ASTG_B;
#pragma unroll
        for (int i = 0; i < 4; i++) {
            int row = ldrow + i * 32;
            uint32_t sa = abase + row * 128 + ((ldcc ^ (row & 7)) << 4);
            const void* g = Ag + (size_t)(bm + row) * K + k0 + ldcc * 8;
            asm volatile("cp.async.cg.shared.global [%0], [%1], 16;"
                         :: "r"(sa), "l"(g));
        }
#pragma unroll
        for (int i = 0; i < 4; i++) {
            int row = ldrow + i * 32;
            uint32_t sa = bbase + row * 128 + ((ldcc ^ (row & 7)) << 4);
            const void* g = B + (size_t)(bn + row) * K + k0 + ldcc * 8;
            asm volatile("cp.async.cg.shared.global [%0], [%1], 16;"
                         :: "r"(sa), "l"(g));
        }
    };

    load_stage(0);
    asm volatile("cp.async.commit_group;");

    const int lr  = lane & 7;
    const int sub = lane >> 3;

    for (int t = 0; t < T; ++t) {
        if (t + 1 < T) load_stage(t + 1);
        asm volatile("cp.async.commit_group;");
        asm volatile("cp.async.wait_group 1;");
        __syncthreads();

        const int s = t & 1;
        const uint32_t abase = smbase + s * STG_B;
        const uint32_t bbase = abase + ASTG_B;

#pragma unroll
        for (int k16 = 0; k16 < 4; k16++) {
            uint32_t af[4][4];
            uint32_t bf[4][2];
#pragma unroll
            for (int mt = 0; mt < 4; mt++) {
                int row = wm * 64 + mt * 16 + lr + (sub & 1) * 8;
                int ch  = k16 * 2 + (sub >> 1);
                uint32_t ad = abase + row * 128 + ((ch ^ (row & 7)) << 4);
                asm volatile(
                    "ldmatrix.sync.aligned.m8n8.x4.shared.b16 {%0,%1,%2,%3}, [%4];"
                    : "=r"(af[mt][0]), "=r"(af[mt][1]),
                      "=r"(af[mt][2]), "=r"(af[mt][3]) : "r"(ad));
            }
#pragma unroll
            for (int np = 0; np < 2; np++) {
                int row = wn * 32 + np * 16 + lr + (sub >> 1) * 8;
                int ch  = k16 * 2 + (sub & 1);
                uint32_t bd = bbase + row * 128 + ((ch ^ (row & 7)) << 4);
                asm volatile(
                    "ldmatrix.sync.aligned.m8n8.x4.shared.b16 {%0,%1,%2,%3}, [%4];"
                    : "=r"(bf[np * 2][0]), "=r"(bf[np * 2][1]),
                      "=r"(bf[np * 2 + 1][0]), "=r"(bf[np * 2 + 1][1]) : "r"(bd));
            }
#pragma unroll
            for (int mt = 0; mt < 4; mt++)
#pragma unroll
                for (int nt = 0; nt < 4; nt++)
                    asm volatile(
                        "mma.sync.aligned.m16n8k16.row.col.f32.f16.f16.f32 "
                        "{%0,%1,%2,%3}, {%4,%5,%6,%7}, {%8,%9}, {%0,%1,%2,%3};"
                        : "+f"(acc[mt][nt][0]), "+f"(acc[mt][nt][1]),
                          "+f"(acc[mt][nt][2]), "+f"(acc[mt][nt][3])
                        : "r"(af[mt][0]), "r"(af[mt][1]),
                          "r"(af[mt][2]), "r"(af[mt][3]),
                          "r"(bf[nt][0]), "r"(bf[nt][1]));
        }
        __syncthreads();
    }

    const int crow0 = bm + wm * 64 + (lane >> 2);
    const int ccol0 = bn + wn * 32 + (lane & 3) * 2;
#pragma unroll
    for (int mt = 0; mt < 4; mt++) {
#pragma unroll
        for (int nt = 0; nt < 4; nt++) {
            float* p0 = C + (size_t)(crow0 + mt * 16) * Ntot + ccol0 + nt * 8;
            float* p1 = p0 + (size_t)8 * Ntot;
            *(float2*)p0 = make_float2(acc[mt][nt][0], acc[mt][nt][1]);
            *(float2*)p1 = make_float2(acc[mt][nt][2], acc[mt][nt][3]);
        }
    }
}

// ---------------- fp16 2-pass GEMM -> fp16 C (gate path) --------------------------
__global__ __launch_bounds__(256, 2) void gemm_hmma2h_hc(
    const __half* __restrict__ Ah, const __half* __restrict__ Al,
    const __half* __restrict__ B,
    __half* __restrict__ C, int Ntot, int K)
{
    extern __shared__ char smraw[];
    const int tid  = threadIdx.x;
    const int lane = tid & 31;
    const int wid  = tid >> 5;
    const int wm   = wid & 1;
    const int wn   = wid >> 1;
    const int bm   = blockIdx.y * BMt;
    const int bn   = blockIdx.x * BNt;

    const uint32_t smbase = smu32(smraw);
    const int ldrow = tid >> 3;
    const int ldcc  = tid & 7;

    const int TSEG = K >> 6;
    const int T = 2 * TSEG;

    float acc[4][4][4];
#pragma unroll
    for (int a = 0; a < 4; a++)
#pragma unroll
        for (int b = 0; b < 4; b++)
#pragma unroll
            for (int c = 0; c < 4; c++) acc[a][b][c] = 0.f;

    auto load_stage = [&](int t) {
        const int s = t & 1;
        const int seg = t / TSEG;
        const int k0 = (t - seg * TSEG) * BKt;
        const __half* Ag = seg ? Al : Ah;
        const uint32_t abase = smbase + s * STG_B;
        const uint32_t bbase = abase + ASTG_B;
#pragma unroll
        for (int i = 0; i < 4; i++) {
            int row = ldrow + i * 32;
            uint32_t sa = abase + row * 128 + ((ldcc ^ (row & 7)) << 4);
            const void* g = Ag + (size_t)(bm + row) * K + k0 + ldcc * 8;
            asm volatile("cp.async.cg.shared.global [%0], [%1], 16;"
                         :: "r"(sa), "l"(g));
        }
#pragma unroll
        for (int i = 0; i < 4; i++) {
            int row = ldrow + i * 32;
            uint32_t sa = bbase + row * 128 + ((ldcc ^ (row & 7)) << 4);
            const void* g = B + (size_t)(bn + row) * K + k0 + ldcc * 8;
            asm volatile("cp.async.cg.shared.global [%0], [%1], 16;"
                         :: "r"(sa), "l"(g));
        }
    };

    load_stage(0);
    asm volatile("cp.async.commit_group;");

    const int lr  = lane & 7;
    const int sub = lane >> 3;

    for (int t = 0; t < T; ++t) {
        if (t + 1 < T) load_stage(t + 1);
        asm volatile("cp.async.commit_group;");
        asm volatile("cp.async.wait_group 1;");
        __syncthreads();

        const int s = t & 1;
        const uint32_t abase = smbase + s * STG_B;
        const uint32_t bbase = abase + ASTG_B;

#pragma unroll
        for (int k16 = 0; k16 < 4; k16++) {
            uint32_t af[4][4];
            uint32_t bf[4][2];
#pragma unroll
            for (int mt = 0; mt < 4; mt++) {
                int row = wm * 64 + mt * 16 + lr + (sub & 1) * 8;
                int ch  = k16 * 2 + (sub >> 1);
                uint32_t ad = abase + row * 128 + ((ch ^ (row & 7)) << 4);
                asm volatile(
                    "ldmatrix.sync.aligned.m8n8.x4.shared.b16 {%0,%1,%2,%3}, [%4];"
                    : "=r"(af[mt][0]), "=r"(af[mt][1]),
                      "=r"(af[mt][2]), "=r"(af[mt][3]) : "r"(ad));
            }
#pragma unroll
            for (int np = 0; np < 2; np++) {
                int row = wn * 32 + np * 16 + lr + (sub >> 1) * 8;
                int ch  = k16 * 2 + (sub & 1);
                uint32_t bd = bbase + row * 128 + ((ch ^ (row & 7)) << 4);
                asm volatile(
                    "ldmatrix.sync.aligned.m8n8.x4.shared.b16 {%0,%1,%2,%3}, [%4];"
                    : "=r"(bf[np * 2][0]), "=r"(bf[np * 2][1]),
                      "=r"(bf[np * 2 + 1][0]), "=r"(bf[np * 2 + 1][1]) : "r"(bd));
            }
#pragma unroll
            for (int mt = 0; mt < 4; mt++)
#pragma unroll
                for (int nt = 0; nt < 4; nt++)
                    asm volatile(
                        "mma.sync.aligned.m16n8k16.row.col.f32.f16.f16.f32 "
                        "{%0,%1,%2,%3}, {%4,%5,%6,%7}, {%8,%9}, {%0,%1,%2,%3};"
                        : "+f"(acc[mt][nt][0]), "+f"(acc[mt][nt][1]),
                          "+f"(acc[mt][nt][2]), "+f"(acc[mt][nt][3])
                        : "r"(af[mt][0]), "r"(af[mt][1]),
                          "r"(af[mt][2]), "r"(af[mt][3]),
                          "r"(bf[nt][0]), "r"(bf[nt][1]));
        }
        __syncthreads();
    }

    const int crow0 = bm + wm * 64 + (lane >> 2);
    const int ccol0 = bn + wn * 32 + (lane & 3) * 2;
#pragma unroll
    for (int mt = 0; mt < 4; mt++) {
#pragma unroll
        for (int nt = 0; nt < 4; nt++) {
            __half* p0 = C + (size_t)(crow0 + mt * 16) * Ntot + ccol0 + nt * 8;
            __half* p1 = p0 + (size_t)8 * Ntot;
            __half2 a(__float2half_rn(acc[mt][nt][0]), __float2half_rn(acc[mt][nt][1]));
            __half2 b(__float2half_rn(acc[mt][nt][2]), __float2half_rn(acc[mt][nt][3]));
            *(uint32_t*)p0 = *(uint32_t*)&a;
            *(uint32_t*)p1 = *(uint32_t*)&b;
        }
    }
}

// ---------------- RoPE tables (double precision, once) ----------------------------
__global__ void rope_table_kernel()
{
    int idx = blockIdx.x * 256 + threadIdx.x;
    int l = idx >> 6, j = idx & 63;
    double invf = exp(-((double)(2 * j) / 128.0) * log(10000.0));
    double ang = (double)l * invf;
    g_ctab[idx] = (float)cos(ang);
    g_stab[idx] = (float)sin(ang);
}

__global__ void rope_apply_kernel()
{
    int idx = blockIdx.x * 256 + threadIdx.x;
    int j = idx & 63;
    int t2 = idx >> 6;
    int hh = t2 % (NH + NKV);
    int l  = t2 / (NH + NKV);
    float c = g_ctab[(l << 6) + j];
    float s = g_stab[(l << 6) + j];
    float* base = (hh < NH) ? g_q + (size_t)l * QDIM + hh * DH
                            : g_k + (size_t)l * KVDIM + (hh - NH) * DH;
    float x0 = base[j], x1 = base[j + 64];
    base[j]      = x0 * c - x1 * s;
    base[j + 64] = x1 * c + x0 * s;
}

// ---------------- dt = softplus(hs @ Win^T + bias), W-tiled -----------------------
__global__ __launch_bounds__(128) void dt_kernel(
    const float* __restrict__ hs, const float* __restrict__ Win,
    const float* __restrict__ dtb)
{
    __shared__ float Wt[NH][132];
    const int row = blockIdx.x * 128 + threadIdx.x;
    const int tid = threadIdx.x;
    float acc[NH];
#pragma unroll
    for (int h = 0; h < NH; h++) acc[h] = 0.f;

    for (int k0 = 0; k0 < HIDDEN; k0 += 128) {
        __syncthreads();
        for (int t = tid; t < NH * 32; t += 128) {
            int h = t >> 5, kq = (t & 31) * 4;
            float4 w = *(const float4*)&Win[(size_t)h * HIDDEN + k0 + kq];
            *(float4*)&Wt[h][kq] = w;
        }
        __syncthreads();
        const float* hrow = hs + (size_t)row * HIDDEN + k0;
        for (int kk = 0; kk < 128; kk += 4) {
            float4 x = *(const float4*)(hrow + kk);
#pragma unroll
            for (int h = 0; h < NH; h++) {
                float4 w = *(const float4*)&Wt[h][kk];
                acc[h] += x.x * w.x + x.y * w.y + x.z * w.z + x.w * w.w;
            }
        }
    }
#pragma unroll
    for (int h = 0; h < NH; h++) {
        float s = acc[h] + dtb[h];
        float sp = fmaxf(s, 0.f) + log1pf(expf(-fabsf(s)));
        g_dt[(size_t)row * NH + h] = sp;
    }
}

// ---------------- per-chunk cumulative gate G -------------------------------------
__global__ void cumsum_kernel(const float* __restrict__ Alog)
{
    __shared__ float smv[CHUNK];
    int n = blockIdx.x, h = blockIdx.y, i = threadIdx.x;
    float A = -expf(Alog[h]);
    smv[i] = g_dt[(size_t)(n * CHUNK + i) * NH + h] * A;
    __syncthreads();
    for (int off = 1; off < CHUNK; off <<= 1) {
        float t = (i >= off) ? smv[i - off] : 0.f;
        __syncthreads();
        smv[i] += t;
        __syncthreads();
    }
    g_G[(size_t)h * LSEQ + n * CHUNK + i] = smv[i];
}

// ---------------- kernel A: decayed scores Sd[j][i] (fp16) + chunk states ---------
__global__ __launch_bounds__(256) void chunk_intra_kernel()
{
    extern __shared__ float sm[];
    float* U = sm;
    float* V = sm + 128 * PADA;
    __shared__ float Gsm[CHUNK];
    __shared__ float dsm[CHUNK];

    const int n = blockIdx.x, h = blockIdx.y;
    const int tid = threadIdx.x;
    const int tcol = tid & 15, trow = tid >> 4;
    const int lrow = tid >> 5;
    const int lane4 = (tid & 31) * 4;
    const int kvb = (h >> 2) * DH;

    if (tid < CHUNK) {
        Gsm[tid] = g_G[(size_t)h * LSEQ + n * CHUNK + tid];
        dsm[tid] = g_dt[(size_t)(n * CHUNK + tid) * NH + h];
    }
    for (int p = 0; p < 16; p++) {
        int i = p * 8 + lrow;
        float4 qv = *(const float4*)&g_q[(size_t)(n * CHUNK + i) * QDIM + h * DH + lane4];
        U[(lane4 + 0) * PADA + i] = qv.x; U[(lane4 + 1) * PADA + i] = qv.y;
        U[(lane4 + 2) * PADA + i] = qv.z; U[(lane4 + 3) * PADA + i] = qv.w;
        float4 kv = *(const float4*)&g_k[(size_t)(n * CHUNK + i) * KVDIM + kvb + lane4];
        V[(lane4 + 0) * PADA + i] = kv.x; V[(lane4 + 1) * PADA + i] = kv.y;
        V[(lane4 + 2) * PADA + i] = kv.z; V[(lane4 + 3) * PADA + i] = kv.w;
    }
    __syncthreads();

    float acc[8][8];
#pragma unroll
    for (int r = 0; r < 8; r++)
#pragma unroll
        for (int c = 0; c < 8; c++) acc[r][c] = 0.f;

#pragma unroll 4
    for (int kk = 0; kk < 128; kk++) {
        float a[8], b[8];
#pragma unroll
        for (int r = 0; r < 8; r++) a[r] = V[kk * PADA + trow * 8 + r];
#pragma unroll
        for (int c = 0; c < 8; c++) b[c] = U[kk * PADA + tcol * 8 + c];
#pragma unroll
        for (int r = 0; r < 8; r++)
#pragma unroll
            for (int c = 0; c < 8; c++) acc[r][c] += a[r] * b[c];
    }
    const size_t off = ((size_t)h * NCHUNK + n) * (CHUNK * CHUNK);
#pragma unroll
    for (int r = 0; r < 8; r++) {
        int j = trow * 8 + r;
        float Gj = Gsm[j];
        float vv[8];
#pragma unroll
        for (int c = 0; c < 8; c++) {
            int i = tcol * 8 + c;
            vv[c] = (i >= j) ? acc[r][c] * expf(Gsm[i] - Gj) : 0.f;
        }
        __half2 p0(__float2half_rn(vv[0]), __float2half_rn(vv[1]));
        __half2 p1(__float2half_rn(vv[2]), __float2half_rn(vv[3]));
        __half2 p2(__float2half_rn(vv[4]), __float2half_rn(vv[5]));
        __half2 p3(__float2half_rn(vv[6]), __float2half_rn(vv[7]));
        uint4 pk;
        pk.x = *(uint32_t*)&p0; pk.y = *(uint32_t*)&p1;
        pk.z = *(uint32_t*)&p2; pk.w = *(uint32_t*)&p3;
        *(uint4*)&g_S[off + (size_t)j * CHUNK + tcol * 8] = pk;
    }
    __syncthreads();

    float Glast = Gsm[CHUNK - 1];
    for (int p = 0; p < 16; p++) {
        int j = p * 8 + lrow;
        float w = expf(Glast - Gsm[j]);
        float dt = dsm[j];
        float4 kv = *(const float4*)&g_k[(size_t)(n * CHUNK + j) * KVDIM + kvb + lane4];
        V[j * PADA + lane4 + 0] = kv.x * w; V[j * PADA + lane4 + 1] = kv.y * w;
        V[j * PADA + lane4 + 2] = kv.z * w; V[j * PADA + lane4 + 3] = kv.w * w;
        float4 vv = *(const float4*)&g_v[(size_t)(n * CHUNK + j) * KVDIM + kvb + lane4];
        U[j * PADA + lane4 + 0] = vv.x * dt; U[j * PADA + lane4 + 1] = vv.y * dt;
        U[j * PADA + lane4 + 2] = vv.z * dt; U[j * PADA + lane4 + 3] = vv.w * dt;
    }
    __syncthreads();

    float acc2[8][8];
#pragma unroll
    for (int r = 0; r < 8; r++)
#pragma unroll
        for (int c = 0; c < 8; c++) acc2[r][c] = 0.f;

#pragma unroll 4
    for (int kk = 0; kk < 128; kk++) {
        float a[8], b[8];
#pragma unroll
        for (int r = 0; r < 8; r++) a[r] = V[kk * PADA + trow * 8 + r];
#pragma unroll
        for (int c = 0; c < 8; c++) b[c] = U[kk * PADA + tcol * 8 + c];
#pragma unroll
        for (int r = 0; r < 8; r++)
#pragma unroll
            for (int c = 0; c < 8; c++) acc2[r][c] += a[r] * b[c];
    }
    const size_t off2 = ((size_t)h * NCHUNK + n) * (DH * DH);
#pragma unroll
    for (int r = 0; r < 8; r++) {
        int d = trow * 8 + r;
#pragma unroll
        for (int c = 0; c < 8; c++)
            g_cs[off2 + (size_t)d * DH + tcol * 8 + c] = acc2[r][c];
    }
}

// ---------------- inter-chunk recurrent scan --------------------------------------
__global__ void scan_kernel()
{
    int h = blockIdx.y;
    size_t base = (size_t)blockIdx.x * 1024 + threadIdx.x * 4;
    float4 s = make_float4(0.f, 0.f, 0.f, 0.f);
    for (int nn = 0; nn < NCHUNK; nn++) {
        size_t o = ((size_t)h * NCHUNK + nn) * (DH * DH) + base;
        *(float4*)&g_prev[o] = s;
        float dec = expf(g_G[(size_t)h * LSEQ + nn * CHUNK + CHUNK - 1]);
        float4 cs = *(const float4*)&g_cs[o];
        s.x = s.x * dec + cs.x; s.y = s.y * dec + cs.y;
        s.z = s.z * dec + cs.z; s.w = s.w * dec + cs.w;
    }
}

// ---------------- kernel B: y_intra + y_inter + RMS + SiLU gate -> fp16 split -----
__global__ __launch_bounds__(256) void chunk_out_kernel(const float* __restrict__ gnw)
{
    extern __shared__ float sm[];
    float* V = sm;
    float* U = sm + 128 * PADA;
    __shared__ float Gsm[CHUNK];
    __shared__ float dsm[CHUNK];
    __shared__ float red[256];
    __shared__ float rinv[CHUNK];

    const int n = blockIdx.x, h = blockIdx.y;
    const int tid = threadIdx.x;
    const int tcol = tid & 15, trow = tid >> 4;
    const int lrow = tid >> 5;
    const int lane4 = (tid & 31) * 4;
    const int kvb = (h >> 2) * DH;
    const size_t offS = ((size_t)h * NCHUNK + n) * (CHUNK * CHUNK);
    const size_t off  = ((size_t)h * NCHUNK + n) * (DH * DH);

    if (tid < CHUNK) {
        Gsm[tid] = g_G[(size_t)h * LSEQ + n * CHUNK + tid];
        dsm[tid] = g_dt[(size_t)(n * CHUNK + tid) * NH + h];
    }
    for (int t = tid * 8; t < CHUNK * CHUNK; t += 2048) {
        uint4 sv = *(const uint4*)&g_S[offS + t];
        int j = t >> 7, i = t & 127;
        __half2* hp = (__half2*)&sv;
        float2 f0 = __half22float2(hp[0]);
        float2 f1 = __half22float2(hp[1]);
        float2 f2 = __half22float2(hp[2]);
        float2 f3 = __half22float2(hp[3]);
        V[j * PADA + i + 0] = f0.x; V[j * PADA + i + 1] = f0.y;
        V[j * PADA + i + 2] = f1.x; V[j * PADA + i + 3] = f1.y;
        V[j * PADA + i + 4] = f2.x; V[j * PADA + i + 5] = f2.y;
        V[j * PADA + i + 6] = f3.x; V[j * PADA + i + 7] = f3.y;
    }
    __syncthreads();
    for (int p = 0; p < 16; p++) {
        int j = p * 8 + lrow;
        float dt = dsm[j];
        float4 vv = *(const float4*)&g_v[(size_t)(n * CHUNK + j) * KVDIM + kvb + lane4];
        U[j * PADA + lane4 + 0] = vv.x * dt; U[j * PADA + lane4 + 1] = vv.y * dt;
        U[j * PADA + lane4 + 2] = vv.z * dt; U[j * PADA + lane4 + 3] = vv.w * dt;
    }
    __syncthreads();

    float acc[8][8];
#pragma unroll
    for (int r = 0; r < 8; r++)
#pragma unroll
        for (int c = 0; c < 8; c++) acc[r][c] = 0.f;

#pragma unroll 4
    for (int kk = 0; kk < 128; kk++) {
        float a[8], b[8];
#pragma unroll
        for (int r = 0; r < 8; r++) a[r] = V[kk * PADA + trow * 8 + r];
#pragma unroll
        for (int c = 0; c < 8; c++) b[c] = U[kk * PADA + tcol * 8 + c];
#pragma unroll
        for (int r = 0; r < 8; r++)
#pragma unroll
            for (int c = 0; c < 8; c++) acc[r][c] += a[r] * b[c];
    }
    __syncthreads();

    for (int p = 0; p < 16; p++) {
        int i = p * 8 + lrow;
        float eg = expf(Gsm[i]);
        float4 qv = *(const float4*)&g_q[(size_t)(n * CHUNK + i) * QDIM + h * DH + lane4];
        V[(lane4 + 0) * PADA + i] = qv.x * eg; V[(lane4 + 1) * PADA + i] = qv.y * eg;
        V[(lane4 + 2) * PADA + i] = qv.z * eg; V[(lane4 + 3) * PADA + i] = qv.w * eg;
    }
    for (int t = tid * 4; t < DH * DH; t += 1024) {
        float4 pv = *(const float4*)&g_prev[off + t];
        int d = t >> 7, e = t & 127;
        U[d * PADA + e + 0] = pv.x; U[d * PADA + e + 1] = pv.y;
        U[d * PADA + e + 2] = pv.z; U[d * PADA + e + 3] = pv.w;
    }
    __syncthreads();

#pragma unroll 4
    for (int kk = 0; kk < 128; kk++) {
        float a[8], b[8];
#pragma unroll
        for (int r = 0; r < 8; r++) a[r] = V[kk * PADA + trow * 8 + r];
#pragma unroll
        for (int c = 0; c < 8; c++) b[c] = U[kk * PADA + tcol * 8 + c];
#pragma unroll
        for (int r = 0; r < 8; r++)
#pragma unroll
            for (int c = 0; c < 8; c++) acc[r][c] += a[r] * b[c];
    }
    __syncthreads();

#pragma unroll
    for (int r = 0; r < 8; r++)
#pragma unroll
        for (int c = 0; c < 8; c++)
            V[(trow * 8 + r) * PADA + tcol * 8 + c] = acc[r][c];
    __syncthreads();

    {
        int row = tid >> 1, half = tid & 1;
        float ss = 0.f;
        for (int e = half * 64; e < half * 64 + 64; e++) {
            float v = V[row * PADA + e];
            ss += v * v;
        }
        red[tid] = ss;
    }
    __syncthreads();
    if (tid < CHUNK)
        rinv[tid] = rsqrtf((red[tid * 2] + red[tid * 2 + 1]) * (1.0f / DH) + 1e-5f);
    __syncthreads();

    for (int t = tid * 2; t < CHUNK * DH; t += 512) {
        int i = t >> 7, e = t & 127;
        int l = n * CHUNK + i;
        float ri = rinv[i];
        float v0 = V[i * PADA + e + 0] * ri * gnw[e + 0];
        float v1 = V[i * PADA + e + 1] * ri * gnw[e + 1];
        uint32_t gu = *(const uint32_t*)&g_gateh[(size_t)l * QDIM + h * DH + e];
        float2 gt = __half22float2(*(__half2*)&gu);
        v0 *= gt.x / (1.f + expf(-gt.x));
        v1 *= gt.y / (1.f + expf(-gt.y));
        __half h0 = __float2half_rn(v0);
        __half h1 = __float2half_rn(v1);
        __half l0 = __float2half_rn(v0 - __half2float(h0));
        __half l1 = __float2half_rn(v1 - __half2float(h1));
        __half2 hp(h0, h1), lp(l0, l1);
        *(uint32_t*)&g_yfh[(size_t)l * QDIM + h * DH + e] = *(uint32_t*)&hp;
        *(uint32_t*)&g_yfl[(size_t)l * QDIM + h * DH + e] = *(uint32_t*)&lp;
    }
}

// ---------------- launch -----------------------------------------------------------
extern "C" void kernel_launch(void* const* d_in, const int* in_sizes, int n_in,
                              void* d_out, int out_size)
{
    const float* hs   = (const float*)d_in[0];
    const float* Wq   = (const float*)d_in[1];
    const float* Wk   = (const float*)d_in[2];
    const float* Wv   = (const float*)d_in[3];
    const float* Wo   = (const float*)d_in[4];
    const float* Wg   = (const float*)d_in[5];
    const float* Win  = (const float*)d_in[6];
    const float* dtb  = (const float*)d_in[7];
    const float* Alog = (const float*)d_in[8];
    const float* gnw  = (const float*)d_in[9];
    float* out = (float*)d_out;

    float *q, *k, *v;
    cudaGetSymbolAddress((void**)&q, g_q);
    cudaGetSymbolAddress((void**)&k, g_k);
    cudaGetSymbolAddress((void**)&v, g_v);
    __half* gateh;
    cudaGetSymbolAddress((void**)&gateh, g_gateh);

    __nv_bfloat16 *hsh, *hsl, *Wqh, *Wql, *Wkh, *Wkl, *Wvh, *Wvl;
    cudaGetSymbolAddress((void**)&hsh, g_hsh);  cudaGetSymbolAddress((void**)&hsl, g_hsl);
    cudaGetSymbolAddress((void**)&Wqh, g_Wqh);  cudaGetSymbolAddress((void**)&Wql, g_Wql);
    cudaGetSymbolAddress((void**)&Wkh, g_Wkh);  cudaGetSymbolAddress((void**)&Wkl, g_Wkl);
    cudaGetSymbolAddress((void**)&Wvh, g_Wvh);  cudaGetSymbolAddress((void**)&Wvl, g_Wvl);

    __half *hsfh, *hsfl, *Wgc, *Woc, *yfh, *yfl;
    cudaGetSymbolAddress((void**)&hsfh, g_hsfh);
    cudaGetSymbolAddress((void**)&hsfl, g_hsfl);
    cudaGetSymbolAddress((void**)&Wgc, g_Wgc);
    cudaGetSymbolAddress((void**)&Woc, g_Woc);
    cudaGetSymbolAddress((void**)&yfh, g_yfh);
    cudaGetSymbolAddress((void**)&yfl, g_yfl);

    const int SMEM_AB = 2 * 128 * PADA * (int)sizeof(float);
    cudaFuncSetAttribute(chunk_intra_kernel,
                         cudaFuncAttributeMaxDynamicSharedMemorySize, SMEM_AB);
    cudaFuncSetAttribute(chunk_out_kernel,
                         cudaFuncAttributeMaxDynamicSharedMemorySize, SMEM_AB);
    cudaFuncSetAttribute(gemm_hmma3,
                         cudaFuncAttributeMaxDynamicSharedMemorySize, GEMM_SMEM);
    cudaFuncSetAttribute(gemm_hmma2h,
                         cudaFuncAttributeMaxDynamicSharedMemorySize, GEMM_SMEM);
    cudaFuncSetAttribute(gemm_hmma2h_hc,
                         cudaFuncAttributeMaxDynamicSharedMemorySize, GEMM_SMEM);

    const size_t NBIG = (size_t)HIDDEN * HIDDEN;      // 16M
    const size_t NSML = (size_t)KVDIM * HIDDEN;       // 4M

    cvt_hs_all<<<(int)(NBIG / 1024), 256>>>(hs);
    cvt_split<<<(int)(NBIG / 1024), 256>>>(Wq, Wqh, Wql, NBIG);
    cvt_split<<<(int)(NSML / 1024), 256>>>(Wk, Wkh, Wkl, NSML);
    cvt_split<<<(int)(NSML / 1024), 256>>>(Wv, Wvh, Wvl, NSML);
    cvt_h<<<(int)(NBIG / 1024), 256>>>(Wg, Wgc, NBIG);
    gemm_hmma3<<<dim3(QDIM / BNt, LSEQ / BMt),  256, GEMM_SMEM>>>(hsh, hsl, Wqh, Wql, q, QDIM,  HIDDEN);
    gemm_hmma3<<<dim3(KVDIM / BNt, LSEQ / BMt), 256, GEMM_SMEM>>>(hsh, hsl, Wkh, Wkl, k, KVDIM, HIDDEN);
    gemm_hmma3<<<dim3(KVDIM / BNt, LSEQ / BMt), 256, GEMM_SMEM>>>(hsh, hsl, Wvh, Wvl, v, KVDIM, HIDDEN);
    gemm_hmma2h_hc<<<dim3(QDIM / BNt, LSEQ / BMt), 256, GEMM_SMEM>>>(hsfh, hsfl, Wgc, gateh, QDIM, HIDDEN);

    dt_kernel<<<LSEQ / 128, 128>>>(hs, Win, dtb);
    rope_table_kernel<<<(LSEQ * 64) / 256, 256>>>();
    rope_apply_kernel<<<(LSEQ * (NH + NKV) * 64) / 256, 256>>>();
    cumsum_kernel<<<dim3(NCHUNK, NH), CHUNK>>>(Alog);
    chunk_intra_kernel<<<dim3(NCHUNK, NH), 256, SMEM_AB>>>();
    scan_kernel<<<dim3(16, NH), 256>>>();
    chunk_out_kernel<<<dim3(NCHUNK, NH), 256, SMEM_AB>>>(gnw);

    cvt_h<<<(int)(NBIG / 1024), 256>>>(Wo, Woc, NBIG);
    gemm_hmma2h<<<dim3(HIDDEN / BNt, LSEQ / BMt), 256, GEMM_SMEM>>>(yfh, yfl, Woc, out, HIDDEN, HIDDEN);
}